// round 8
// baseline (speedup 1.0000x reference)
#include <cuda_runtime.h>
#include <cstdint>

// TPThird: per-sample equivariant tensor product. NS=48, NV=10, Z=50000.
// x1: (Z,108) = [0e:48 | 1o:10x3 | 1e:10x3]
// x2: (Z,9)   = [0e:1 | 1o:3 | 2e:5]
// weights: (Z,4344), out: (Z,156) = [r0e:48 | r1o:30 | r1e:30 | r0o:48]
//
// One 192-thread block per sample (10/SM). W row arrives as TWO cp.async.bulk
// chunks with separate mbarriers so the long-loop warps (0/1) start on
// chunk A (w00/w01/w10/w110) while chunk B is still in flight. x1/x2 via LDG
// pre-sync; derived activations overlap the TMA wait. p01 computed on warp 5,
// handed to warp 2 via named barrier 1.

#define X1DIM 108
#define WNUM  4344
#define OUTDIM 156

#define OW00  0
#define OW01  2304
#define OW10  2784
#define OW110 2884
#define OW112 3364
#define OW12  3464
#define OW20  3564
#define OW211 3664
#define OW213 3764
#define OW22  4244

#define CHUNKA_FLOATS 3364   // [0, OW112): w00, w01, w10, w110
#define CHUNKB_FLOATS (WNUM - CHUNKA_FLOATS)

__device__ __forceinline__ uint32_t smem_u32(const void* p) {
    return (uint32_t)__cvta_generic_to_shared(p);
}

__device__ __forceinline__ void mbar_wait(uint32_t mb, uint32_t phase) {
    uint32_t done;
    asm volatile(
        "{\n\t"
        ".reg .pred P;\n\t"
        "WAIT_%=:\n\t"
        "mbarrier.try_wait.parity.shared.b64 P, [%1], %2;\n\t"
        "selp.b32 %0, 1, 0, P;\n\t"
        "@!P bra WAIT_%=;\n\t"
        "}"
        : "=r"(done) : "r"(mb), "r"(phase) : "memory");
}

__global__ __launch_bounds__(192, 10)
void tpthird_kernel(const float* __restrict__ x1,
                    const float* __restrict__ x2,
                    const float* __restrict__ W,
                    float* __restrict__ out)
{
    const int z   = blockIdx.x;
    const int tid = threadIdx.x;
    const int wid = tid >> 5;
    const int lid = tid & 31;

    __shared__ __align__(16) float s_W[WNUM];
    __shared__ __align__(16) float s_x1[X1DIM];
    __shared__ float s_x2[9];
    __shared__ float s_d1o[2][10];                 // warps 0,1
    __shared__ float s_d1e[2][10];                 // warps 4,5
    __shared__ float s_t12[10][3], s_t211[10][3];  // warp 2
    __shared__ float s_t112[10][3], s_t22[10][3];  // warp 3
    __shared__ float s_p01[10];                    // warp 5 -> warp 2
    __shared__ __align__(8) unsigned long long s_mbar[2];

    const uint32_t mbA = smem_u32(&s_mbar[0]);
    const uint32_t mbB = smem_u32(&s_mbar[1]);

    // tid 0: init both barriers, launch both W chunks (A first).
    if (tid == 0) {
        asm volatile("mbarrier.init.shared.b64 [%0], 1;" :: "r"(mbA) : "memory");
        asm volatile("mbarrier.init.shared.b64 [%0], 1;" :: "r"(mbB) : "memory");
        asm volatile("fence.proxy.async.shared::cta;" ::: "memory");
        const float* gW = W + (size_t)z * WNUM;
        asm volatile("mbarrier.arrive.expect_tx.shared.b64 _, [%0], %1;"
                     :: "r"(mbA), "r"((uint32_t)(CHUNKA_FLOATS * 4)) : "memory");
        asm volatile("cp.async.bulk.shared::cta.global.mbarrier::complete_tx::bytes "
                     "[%0], [%1], %2, [%3];"
                     :: "r"(smem_u32(s_W)), "l"(gW),
                        "r"((uint32_t)(CHUNKA_FLOATS * 4)), "r"(mbA) : "memory");
        asm volatile("mbarrier.arrive.expect_tx.shared.b64 _, [%0], %1;"
                     :: "r"(mbB), "r"((uint32_t)(CHUNKB_FLOATS * 4)) : "memory");
        asm volatile("cp.async.bulk.shared::cta.global.mbarrier::complete_tx::bytes "
                     "[%0], [%1], %2, [%3];"
                     :: "r"(smem_u32(s_W + CHUNKA_FLOATS)), "l"(gW + CHUNKA_FLOATS),
                        "r"((uint32_t)(CHUNKB_FLOATS * 4)), "r"(mbB) : "memory");
    }
    // x1/x2 via plain LDG (concurrent with the TMA stream).
    if (tid < X1DIM) {
        s_x1[tid] = __ldg(x1 + (size_t)z * X1DIM + tid);
    } else if (tid < X1DIM + 9) {
        s_x2[tid - X1DIM] = __ldg(x2 + (size_t)z * 9 + (tid - X1DIM));
    }
    __syncthreads();   // covers: mbar init, s_x1, s_x2

    const float N0E  = 0.1313064328597226f;    // sqrt(1/58)
    const float N1O  = 0.1961161351381841f;    // sqrt(3/78)
    const float N1E  = 0.3162277660168379f;    // sqrt(1/10)
    const float N0O  = 0.3162277660168379f;    // sqrt(1/10)
    const float ISQ3 = 0.5773502691896258f;    // 1/sqrt(3)
    const float IS6  = 0.4082482904638630164f; // 1/sqrt(6)
    const float S10  = 0.3162277660168379332f; // 1/sqrt(10)
    const float S30  = 0.1825741858350553712f; // 1/sqrt(30)

    const float x20 = s_x2[0];
    const float b0 = s_x2[1], b1 = s_x2[2], b2 = s_x2[3];

    // ---- per-warp precompute (overlaps the TMA wait), lanes 0-9 ----
    if (wid < 2) {
        if (lid < 10) {
            const int u = lid;
            s_d1o[wid][u] = s_x1[48 + u*3 + 0]*b0 + s_x1[48 + u*3 + 1]*b1
                          + s_x1[48 + u*3 + 2]*b2;
        }
    } else if (wid == 2) {
        if (lid < 10) {
            const int u = lid;
            const float a0 = s_x1[48 + u*3 + 0];
            const float a1 = s_x1[48 + u*3 + 1];
            const float a2 = s_x1[48 + u*3 + 2];
            const float e0 = s_x1[78 + u*3 + 0];
            const float e1 = s_x1[78 + u*3 + 1];
            const float e2 = s_x1[78 + u*3 + 2];
            const float c0 = s_x2[4], c1 = s_x2[5], c2 = s_x2[6];
            const float c3 = s_x2[7], c4 = s_x2[8];
            s_t211[u][0] = (e1*b2 - e2*b1) * IS6;
            s_t211[u][1] = (e2*b0 - e0*b2) * IS6;
            s_t211[u][2] = (e0*b1 - e1*b0) * IS6;
            s_t12[u][0] =  S10*a2*c0 - S30*a0*c2 - S10*a0*c4 + S10*a1*c1;
            s_t12[u][1] =  S10*a2*c3 + S10*a0*c1 + 2.0f*S30*a1*c2;
            s_t12[u][2] = -S30*a2*c2 + S10*a2*c4 + S10*a0*c0 + S10*a1*c3;
        }
    } else if (wid == 3) {
        if (lid < 10) {
            const int u = lid;
            const float a0 = s_x1[48 + u*3 + 0];
            const float a1 = s_x1[48 + u*3 + 1];
            const float a2 = s_x1[48 + u*3 + 2];
            const float e0 = s_x1[78 + u*3 + 0];
            const float e1 = s_x1[78 + u*3 + 1];
            const float e2 = s_x1[78 + u*3 + 2];
            const float c0 = s_x2[4], c1 = s_x2[5], c2 = s_x2[6];
            const float c3 = s_x2[7], c4 = s_x2[8];
            s_t112[u][0] = (a1*b2 - a2*b1) * IS6;
            s_t112[u][1] = (a2*b0 - a0*b2) * IS6;
            s_t112[u][2] = (a0*b1 - a1*b0) * IS6;
            s_t22[u][0] =  S10*e2*c0 - S30*e0*c2 - S10*e0*c4 + S10*e1*c1;
            s_t22[u][1] =  S10*e2*c3 + S10*e0*c1 + 2.0f*S30*e1*c2;
            s_t22[u][2] = -S30*e2*c2 + S10*e2*c4 + S10*e0*c0 + S10*e1*c3;
        }
    } else {
        if (lid < 10) {
            const int u = lid;
            s_d1e[wid - 4][u] = s_x1[78 + u*3 + 0]*b0 + s_x1[78 + u*3 + 1]*b1
                              + s_x1[78 + u*3 + 2]*b2;
        }
    }
    __syncwarp();

    float* __restrict__ oz = out + (size_t)z * OUTDIM;

    // ---- weight contraction ----
    // warps 0-1 -> r0e (chunk A only) | warp 2 -> r1o (A for a10, B for rest)
    // warp 3 -> r1e (B) | warp 4 -> r0o[0..31] (B)
    // warp 5 -> p01 (A) + bar1.arrive + r0o[32..47] (B)
    if (wid < 2) {
        mbar_wait(mbA, 0);
        const int w = tid;
        if (w < 48) {
            float acc = 0.0f;
            #pragma unroll
            for (int u = 0; u < 48; u++)
                acc += s_x1[u] * s_W[OW00 + u*48 + w];
            acc *= x20;
            float acc2 = 0.0f;
            #pragma unroll
            for (int u = 0; u < 10; u++)
                acc2 += s_d1o[wid][u] * s_W[OW110 + u*48 + w];
            oz[w] = N0E * (acc + ISQ3 * acc2);
        }
    } else if (wid == 2) {
        mbar_wait(mbA, 0);
        float a10 = 0.0f;
        const int w30 = (lid < 30) ? lid : 0;   // uniform loop, inactive lanes harmless
        const int w = w30 / 3, j = w30 % 3;
        #pragma unroll
        for (int u = 0; u < 10; u++)
            a10 += s_x1[48 + u*3 + j] * s_W[OW10 + u*10 + w];
        mbar_wait(mbB, 0);
        // wait for warp 5's p01
        asm volatile("bar.sync 1, 64;" ::: "memory");
        if (lid < 30) {
            const float x2j = s_x2[1 + j];
            const float p01 = s_p01[w];
            float a12 = 0.0f, a211 = 0.0f;
            #pragma unroll
            for (int u = 0; u < 10; u++) {
                a12  += s_t12[u][j]  * s_W[OW12  + u*10 + w];
                a211 += s_t211[u][j] * s_W[OW211 + u*10 + w];
            }
            oz[48 + lid] = N1O * (ISQ3 * (x2j * p01 + x20 * a10) + a12 + a211);
        }
    } else if (wid == 3) {
        mbar_wait(mbB, 0);
        if (lid < 30) {
            const int w = lid / 3, k = lid % 3;
            float a112 = 0.0f, a20 = 0.0f, a22 = 0.0f;
            #pragma unroll
            for (int u = 0; u < 10; u++) {
                a112 += s_t112[u][k]       * s_W[OW112 + u*10 + w];
                a20  += s_x1[78 + u*3 + k] * s_W[OW20  + u*10 + w];
                a22  += s_t22[u][k]        * s_W[OW22  + u*10 + w];
            }
            oz[78 + lid] = N1E * (a112 + ISQ3 * x20 * a20 + a22);
        }
    } else if (wid == 4) {
        mbar_wait(mbB, 0);
        const int w = lid;          // r0o[0..31]
        float acc = 0.0f;
        #pragma unroll
        for (int u = 0; u < 10; u++)
            acc += s_d1e[0][u] * s_W[OW213 + u*48 + w];
        oz[108 + w] = N0O * ISQ3 * acc;
    } else {
        // warp 5: p01 (chunk A) for warp 2, then its r0o slice (chunk B)
        mbar_wait(mbA, 0);
        if (lid < 10) {
            const int w = lid;
            float p = 0.0f;
            #pragma unroll
            for (int u = 0; u < 48; u++)
                p += s_x1[u] * s_W[OW01 + u*10 + w];
            s_p01[w] = p;
        }
        asm volatile("bar.arrive 1, 64;" ::: "memory");
        mbar_wait(mbB, 0);
        if (lid < 16) {
            const int w = 32 + lid;  // r0o[32..47]
            float acc = 0.0f;
            #pragma unroll
            for (int u = 0; u < 10; u++)
                acc += s_d1e[1][u] * s_W[OW213 + u*48 + w];
            oz[108 + w] = N0O * ISQ3 * acc;
        }
    }
}

extern "C" void kernel_launch(void* const* d_in, const int* in_sizes, int n_in,
                              void* d_out, int out_size)
{
    const float* x1 = (const float*)d_in[0];
    const float* x2 = (const float*)d_in[1];
    const float* W  = (const float*)d_in[2];
    float* out = (float*)d_out;

    const int Z = in_sizes[0] / X1DIM;
    tpthird_kernel<<<Z, 192>>>(x1, x2, W, out);
}

// round 9
// speedup vs baseline: 1.0005x; 1.0005x over previous
#include <cuda_runtime.h>
#include <cstdint>

// TPThird: per-sample equivariant tensor product. NS=48, NV=10, Z=50000.
// x1: (Z,108) = [0e:48 | 1o:10x3 | 1e:10x3]
// x2: (Z,9)   = [0e:1 | 1o:3 | 2e:5]
// weights: (Z,4344), out: (Z,156) = [r0e:48 | r1o:30 | r1e:30 | r0o:48]
//
// 128-thread blocks, 12 blocks/SM (smem-capped) -> 12 concurrent TMA weight
// streams per SM. Lane-unified loops (per-lane offset/stride/act-select) keep
// every warp divergence-free with a 58-iteration critical path.

#define X1DIM 108
#define WNUM  4344
#define OUTDIM 156

#define OW00  0
#define OW01  2304
#define OW10  2784
#define OW110 2884
#define OW112 3364
#define OW12  3464
#define OW20  3564
#define OW211 3664
#define OW213 3764
#define OW22  4244

__device__ __forceinline__ uint32_t smem_u32(const void* p) {
    return (uint32_t)__cvta_generic_to_shared(p);
}

__device__ __forceinline__ void mbar_wait(uint32_t mb, uint32_t phase) {
    uint32_t done;
    asm volatile(
        "{\n\t"
        ".reg .pred P;\n\t"
        "WAIT_%=:\n\t"
        "mbarrier.try_wait.parity.shared.b64 P, [%1], %2;\n\t"
        "selp.b32 %0, 1, 0, P;\n\t"
        "@!P bra WAIT_%=;\n\t"
        "}"
        : "=r"(done) : "r"(mb), "r"(phase) : "memory");
}

__global__ __launch_bounds__(128, 12)
void tpthird_kernel(const float* __restrict__ x1,
                    const float* __restrict__ x2,
                    const float* __restrict__ W,
                    float* __restrict__ out)
{
    const int z   = blockIdx.x;
    const int tid = threadIdx.x;
    const int wid = tid >> 5;
    const int lid = tid & 31;

    __shared__ __align__(16) float s_W[WNUM];
    __shared__ __align__(16) float s_x1[X1DIM];
    __shared__ float s_x2[9];
    __shared__ float s_d1o0[10];                   // warp0
    __shared__ float s_dw1[2][10];                 // warp1: [0]=d1o, [1]=d1e
    __shared__ float s_d1e2[10];                   // warp2
    __shared__ float s_d1e3[10];                   // warp3
    __shared__ float s_t12[10][3], s_t211[10][3];  // warp2
    __shared__ float s_t112[10][3], s_t22[10][3];  // warp3
    __shared__ float s_p01[10];                    // warp1 -> warp2
    __shared__ __align__(8) unsigned long long s_mbar;

    const uint32_t mb = smem_u32(&s_mbar);

    // tid 0: init barrier, launch W-row TMA.
    if (tid == 0) {
        asm volatile("mbarrier.init.shared.b64 [%0], 1;" :: "r"(mb) : "memory");
        asm volatile("fence.proxy.async.shared::cta;" ::: "memory");
        asm volatile("mbarrier.arrive.expect_tx.shared.b64 _, [%0], %1;"
                     :: "r"(mb), "r"((uint32_t)(WNUM * 4)) : "memory");
        asm volatile("cp.async.bulk.shared::cta.global.mbarrier::complete_tx::bytes "
                     "[%0], [%1], %2, [%3];"
                     :: "r"(smem_u32(s_W)), "l"(W + (size_t)z * WNUM),
                        "r"((uint32_t)(WNUM * 4)), "r"(mb) : "memory");
    }
    // x1/x2 via LDG (concurrent with the TMA stream).
    if (tid < X1DIM) {
        s_x1[tid] = __ldg(x1 + (size_t)z * X1DIM + tid);
    } else if (tid < X1DIM + 9) {
        s_x2[tid - X1DIM] = __ldg(x2 + (size_t)z * 9 + (tid - X1DIM));
    }
    __syncthreads();   // covers: mbar init, s_x1, s_x2

    const float N0E  = 0.1313064328597226f;    // sqrt(1/58)
    const float N1O  = 0.1961161351381841f;    // sqrt(3/78)
    const float N1E  = 0.3162277660168379f;    // sqrt(1/10)
    const float N0O  = 0.3162277660168379f;    // sqrt(1/10)
    const float ISQ3 = 0.5773502691896258f;    // 1/sqrt(3)
    const float IS6  = 0.4082482904638630164f; // 1/sqrt(6)
    const float S10  = 0.3162277660168379332f; // 1/sqrt(10)
    const float S30  = 0.1825741858350553712f; // 1/sqrt(30)

    const float x20 = s_x2[0];
    const float b0 = s_x2[1], b1 = s_x2[2], b2 = s_x2[3];

    // ---- per-warp precompute (overlaps the TMA wait) ----
    if (wid == 0) {
        if (lid < 10) {
            const int u = lid;
            s_d1o0[u] = s_x1[48 + u*3]*b0 + s_x1[48 + u*3 + 1]*b1
                      + s_x1[48 + u*3 + 2]*b2;
        }
    } else if (wid == 1) {
        if (lid < 10) {
            const int u = lid;
            s_dw1[0][u] = s_x1[48 + u*3]*b0 + s_x1[48 + u*3 + 1]*b1
                        + s_x1[48 + u*3 + 2]*b2;
        } else if (lid >= 16 && lid < 26) {
            const int u = lid - 16;
            s_dw1[1][u] = s_x1[78 + u*3]*b0 + s_x1[78 + u*3 + 1]*b1
                        + s_x1[78 + u*3 + 2]*b2;
        }
    } else if (wid == 2) {
        if (lid < 10) {
            const int u = lid;
            const float a0 = s_x1[48 + u*3], a1 = s_x1[48 + u*3 + 1], a2 = s_x1[48 + u*3 + 2];
            const float e0 = s_x1[78 + u*3], e1 = s_x1[78 + u*3 + 1], e2 = s_x1[78 + u*3 + 2];
            const float c0 = s_x2[4], c1 = s_x2[5], c2 = s_x2[6];
            const float c3 = s_x2[7], c4 = s_x2[8];
            s_t211[u][0] = (e1*b2 - e2*b1) * IS6;
            s_t211[u][1] = (e2*b0 - e0*b2) * IS6;
            s_t211[u][2] = (e0*b1 - e1*b0) * IS6;
            s_t12[u][0] =  S10*a2*c0 - S30*a0*c2 - S10*a0*c4 + S10*a1*c1;
            s_t12[u][1] =  S10*a2*c3 + S10*a0*c1 + 2.0f*S30*a1*c2;
            s_t12[u][2] = -S30*a2*c2 + S10*a2*c4 + S10*a0*c0 + S10*a1*c3;
        } else if (lid >= 16 && lid < 26) {
            const int u = lid - 16;
            s_d1e2[u] = s_x1[78 + u*3]*b0 + s_x1[78 + u*3 + 1]*b1
                      + s_x1[78 + u*3 + 2]*b2;
        }
    } else {
        if (lid < 10) {
            const int u = lid;
            const float a0 = s_x1[48 + u*3], a1 = s_x1[48 + u*3 + 1], a2 = s_x1[48 + u*3 + 2];
            const float e0 = s_x1[78 + u*3], e1 = s_x1[78 + u*3 + 1], e2 = s_x1[78 + u*3 + 2];
            const float c0 = s_x2[4], c1 = s_x2[5], c2 = s_x2[6];
            const float c3 = s_x2[7], c4 = s_x2[8];
            s_t112[u][0] = (a1*b2 - a2*b1) * IS6;
            s_t112[u][1] = (a2*b0 - a0*b2) * IS6;
            s_t112[u][2] = (a0*b1 - a1*b0) * IS6;
            s_t22[u][0] =  S10*e2*c0 - S30*e0*c2 - S10*e0*c4 + S10*e1*c1;
            s_t22[u][1] =  S10*e2*c3 + S10*e0*c1 + 2.0f*S30*e1*c2;
            s_t22[u][2] = -S30*e2*c2 + S10*e2*c4 + S10*e0*c0 + S10*e1*c3;
        } else if (lid >= 16 && lid < 26) {
            const int u = lid - 16;
            s_d1e3[u] = s_x1[78 + u*3]*b0 + s_x1[78 + u*3 + 1]*b1
                      + s_x1[78 + u*3 + 2]*b2;
        }
    }
    __syncwarp();

    mbar_wait(mb, 0);   // weights landed

    float* __restrict__ oz = out + (size_t)z * OUTDIM;

    if (wid == 0) {
        // r0e[0..31]: 48-it + 10-it
        const int w = lid;
        float acc = 0.0f;
        #pragma unroll
        for (int u = 0; u < 48; u++)
            acc += s_x1[u] * s_W[OW00 + u*48 + w];
        acc *= x20;
        float acc2 = 0.0f;
        #pragma unroll
        for (int u = 0; u < 10; u++)
            acc2 += s_d1o0[u] * s_W[OW110 + u*48 + w];
        oz[w] = N0E * (acc + ISQ3 * acc2);
    } else if (wid == 1) {
        // Unified 48-loop: lanes 0-15 -> r0e[32+l] (stride 48),
        //                  lanes 16-25 -> p01[l-16] (stride 10), 26-31 dummy.
        const bool is_r0e = (lid < 16);
        const int  pl     = (lid >= 16 && lid < 26) ? (lid - 16) : 9;
        const int  off    = is_r0e ? (OW00 + 32 + lid) : (OW01 + pl);
        const int  str    = is_r0e ? 48 : 10;
        float acc = 0.0f;
        int idx = off;
        #pragma unroll
        for (int u = 0; u < 48; u++) {
            acc += s_x1[u] * s_W[idx];
            idx += str;
        }
        if (lid >= 16 && lid < 26)
            s_p01[lid - 16] = acc;
        __syncwarp();
        asm volatile("bar.arrive 1, 64;" ::: "memory");
        // Unified 10-loop: lanes 0-15 -> w110 tail (act d1o),
        //                  lanes 16-25 -> r0o[l-16] (act d1e), 26-31 dummy.
        const int sel  = is_r0e ? 0 : 1;
        const int off2 = is_r0e ? (OW110 + 32 + lid) : (OW213 + pl);
        float acc2 = 0.0f;
        int idx2 = off2;
        #pragma unroll
        for (int u = 0; u < 10; u++) {
            acc2 += s_dw1[sel][u] * s_W[idx2];
            idx2 += 48;
        }
        if (is_r0e)
            oz[32 + lid] = N0E * (acc * x20 + ISQ3 * acc2);
        else if (lid < 26)
            oz[108 + pl] = N0O * ISQ3 * acc2;
    } else if (wid == 2) {
        // r1o trio (30 it), then combine with p01, then r0o[10..41] (10 it).
        const int w30 = (lid < 30) ? lid : 0;
        const int w = w30 / 3, j = w30 % 3;
        float a10 = 0.0f, a12 = 0.0f, a211 = 0.0f;
        #pragma unroll
        for (int u = 0; u < 10; u++) {
            a10  += s_x1[48 + u*3 + j] * s_W[OW10  + u*10 + w];
            a12  += s_t12[u][j]        * s_W[OW12  + u*10 + w];
            a211 += s_t211[u][j]       * s_W[OW211 + u*10 + w];
        }
        asm volatile("bar.sync 1, 64;" ::: "memory");
        if (lid < 30) {
            const float x2j = s_x2[1 + j];
            oz[48 + lid] = N1O * (ISQ3 * (x2j * s_p01[w] + x20 * a10) + a12 + a211);
        }
        // r0o[10..41]
        const int w2 = 10 + lid;
        float acc = 0.0f;
        #pragma unroll
        for (int u = 0; u < 10; u++)
            acc += s_d1e2[u] * s_W[OW213 + u*48 + w2];
        oz[108 + w2] = N0O * ISQ3 * acc;
    } else {
        // r1e trio (30 it), then r0o[42..47] (10 it, lanes 0-5).
        const int w30 = (lid < 30) ? lid : 0;
        const int w = w30 / 3, k = w30 % 3;
        float a112 = 0.0f, a20 = 0.0f, a22 = 0.0f;
        #pragma unroll
        for (int u = 0; u < 10; u++) {
            a112 += s_t112[u][k]       * s_W[OW112 + u*10 + w];
            a20  += s_x1[78 + u*3 + k] * s_W[OW20  + u*10 + w];
            a22  += s_t22[u][k]        * s_W[OW22  + u*10 + w];
        }
        if (lid < 30)
            oz[78 + lid] = N1E * (a112 + ISQ3 * x20 * a20 + a22);
        // r0o[42..47] on lanes 0-5 (uniform loop, predicated store)
        const int w2 = 42 + ((lid < 6) ? lid : 0);
        float acc = 0.0f;
        #pragma unroll
        for (int u = 0; u < 10; u++)
            acc += s_d1e3[u] * s_W[OW213 + u*48 + w2];
        if (lid < 6)
            oz[108 + w2] = N0O * ISQ3 * acc;
    }
}

extern "C" void kernel_launch(void* const* d_in, const int* in_sizes, int n_in,
                              void* d_out, int out_size)
{
    const float* x1 = (const float*)d_in[0];
    const float* x2 = (const float*)d_in[1];
    const float* W  = (const float*)d_in[2];
    float* out = (float*)d_out;

    const int Z = in_sizes[0] / X1DIM;
    tpthird_kernel<<<Z, 128>>>(x1, x2, W, out);
}

// round 10
// speedup vs baseline: 1.0652x; 1.0647x over previous
#include <cuda_runtime.h>
#include <cstdint>

// TPThird: per-sample equivariant tensor product. NS=48, NV=10, Z=50000.
// x1: (Z,108) = [0e:48 | 1o:10x3 | 1e:10x3]
// x2: (Z,9)   = [0e:1 | 1o:3 | 2e:5]
// weights: (Z,4344), out: (Z,156) = [r0e:48 | r1o:30 | r1e:30 | r0o:48]
//
// One 192-thread block per sample (10/SM). W row via cp.async.bulk with
// L2::evict_first policy (pure streaming); x1/x2 via __ldcs pre-sync;
// outputs via __stcs. Warp-balanced contraction (p01 on warp 5, named bar 1).

#define X1DIM 108
#define WNUM  4344
#define OUTDIM 156

#define OW00  0
#define OW01  2304
#define OW10  2784
#define OW110 2884
#define OW112 3364
#define OW12  3464
#define OW20  3564
#define OW211 3664
#define OW213 3764
#define OW22  4244

__device__ __forceinline__ uint32_t smem_u32(const void* p) {
    return (uint32_t)__cvta_generic_to_shared(p);
}

__device__ __forceinline__ void mbar_wait(uint32_t mb, uint32_t phase) {
    uint32_t done;
    asm volatile(
        "{\n\t"
        ".reg .pred P;\n\t"
        "WAIT_%=:\n\t"
        "mbarrier.try_wait.parity.shared.b64 P, [%1], %2;\n\t"
        "selp.b32 %0, 1, 0, P;\n\t"
        "@!P bra WAIT_%=;\n\t"
        "}"
        : "=r"(done) : "r"(mb), "r"(phase) : "memory");
}

__global__ __launch_bounds__(192, 10)
void tpthird_kernel(const float* __restrict__ x1,
                    const float* __restrict__ x2,
                    const float* __restrict__ W,
                    float* __restrict__ out)
{
    const int z   = blockIdx.x;
    const int tid = threadIdx.x;
    const int wid = tid >> 5;
    const int lid = tid & 31;

    __shared__ __align__(16) float s_W[WNUM];
    __shared__ __align__(16) float s_x1[X1DIM];
    __shared__ float s_x2[9];
    __shared__ float s_d1o[2][10];                 // warps 0,1
    __shared__ float s_d1e[2][10];                 // warps 4,5
    __shared__ float s_t12[10][3], s_t211[10][3];  // warp 2
    __shared__ float s_t112[10][3], s_t22[10][3];  // warp 3
    __shared__ float s_p01[10];                    // warp 5 -> warp 2
    __shared__ __align__(8) unsigned long long s_mbar;

    const uint32_t mb = smem_u32(&s_mbar);

    // tid 0: init barrier and launch the W-row TMA with evict-first policy.
    if (tid == 0) {
        asm volatile("mbarrier.init.shared.b64 [%0], 1;" :: "r"(mb) : "memory");
        asm volatile("fence.proxy.async.shared::cta;" ::: "memory");
        asm volatile("mbarrier.arrive.expect_tx.shared.b64 _, [%0], %1;"
                     :: "r"(mb), "r"((uint32_t)(WNUM * 4)) : "memory");
        uint64_t pol;
        asm volatile("createpolicy.fractional.L2::evict_first.b64 %0, 1.0;"
                     : "=l"(pol));
        asm volatile("cp.async.bulk.shared::cta.global.mbarrier::complete_tx::bytes"
                     ".L2::cache_hint [%0], [%1], %2, [%3], %4;"
                     :: "r"(smem_u32(s_W)), "l"(W + (size_t)z * WNUM),
                        "r"((uint32_t)(WNUM * 4)), "r"(mb), "l"(pol) : "memory");
    }
    // x1/x2 via streaming LDG (concurrent with the TMA stream).
    if (tid < X1DIM) {
        s_x1[tid] = __ldcs(x1 + (size_t)z * X1DIM + tid);
    } else if (tid < X1DIM + 9) {
        s_x2[tid - X1DIM] = __ldcs(x2 + (size_t)z * 9 + (tid - X1DIM));
    }
    __syncthreads();   // covers: mbar init, s_x1, s_x2

    const float N0E  = 0.1313064328597226f;    // sqrt(1/58)
    const float N1O  = 0.1961161351381841f;    // sqrt(3/78)
    const float N1E  = 0.3162277660168379f;    // sqrt(1/10)
    const float N0O  = 0.3162277660168379f;    // sqrt(1/10)
    const float ISQ3 = 0.5773502691896258f;    // 1/sqrt(3)
    const float IS6  = 0.4082482904638630164f; // 1/sqrt(6)
    const float S10  = 0.3162277660168379332f; // 1/sqrt(10)
    const float S30  = 0.1825741858350553712f; // 1/sqrt(30)

    const float x20 = s_x2[0];
    const float b0 = s_x2[1], b1 = s_x2[2], b2 = s_x2[3];

    // ---- per-warp precompute (overlaps the TMA wait), lanes 0-9 ----
    if (wid < 2) {
        if (lid < 10) {
            const int u = lid;
            s_d1o[wid][u] = s_x1[48 + u*3 + 0]*b0 + s_x1[48 + u*3 + 1]*b1
                          + s_x1[48 + u*3 + 2]*b2;
        }
    } else if (wid == 2) {
        if (lid < 10) {
            const int u = lid;
            const float a0 = s_x1[48 + u*3 + 0];
            const float a1 = s_x1[48 + u*3 + 1];
            const float a2 = s_x1[48 + u*3 + 2];
            const float e0 = s_x1[78 + u*3 + 0];
            const float e1 = s_x1[78 + u*3 + 1];
            const float e2 = s_x1[78 + u*3 + 2];
            const float c0 = s_x2[4], c1 = s_x2[5], c2 = s_x2[6];
            const float c3 = s_x2[7], c4 = s_x2[8];
            s_t211[u][0] = (e1*b2 - e2*b1) * IS6;
            s_t211[u][1] = (e2*b0 - e0*b2) * IS6;
            s_t211[u][2] = (e0*b1 - e1*b0) * IS6;
            s_t12[u][0] =  S10*a2*c0 - S30*a0*c2 - S10*a0*c4 + S10*a1*c1;
            s_t12[u][1] =  S10*a2*c3 + S10*a0*c1 + 2.0f*S30*a1*c2;
            s_t12[u][2] = -S30*a2*c2 + S10*a2*c4 + S10*a0*c0 + S10*a1*c3;
        }
    } else if (wid == 3) {
        if (lid < 10) {
            const int u = lid;
            const float a0 = s_x1[48 + u*3 + 0];
            const float a1 = s_x1[48 + u*3 + 1];
            const float a2 = s_x1[48 + u*3 + 2];
            const float e0 = s_x1[78 + u*3 + 0];
            const float e1 = s_x1[78 + u*3 + 1];
            const float e2 = s_x1[78 + u*3 + 2];
            const float c0 = s_x2[4], c1 = s_x2[5], c2 = s_x2[6];
            const float c3 = s_x2[7], c4 = s_x2[8];
            s_t112[u][0] = (a1*b2 - a2*b1) * IS6;
            s_t112[u][1] = (a2*b0 - a0*b2) * IS6;
            s_t112[u][2] = (a0*b1 - a1*b0) * IS6;
            s_t22[u][0] =  S10*e2*c0 - S30*e0*c2 - S10*e0*c4 + S10*e1*c1;
            s_t22[u][1] =  S10*e2*c3 + S10*e0*c1 + 2.0f*S30*e1*c2;
            s_t22[u][2] = -S30*e2*c2 + S10*e2*c4 + S10*e0*c0 + S10*e1*c3;
        }
    } else {
        if (lid < 10) {
            const int u = lid;
            s_d1e[wid - 4][u] = s_x1[78 + u*3 + 0]*b0 + s_x1[78 + u*3 + 1]*b1
                              + s_x1[78 + u*3 + 2]*b2;
        }
    }
    __syncwarp();

    mbar_wait(mb, 0);   // weights landed

    float* __restrict__ oz = out + (size_t)z * OUTDIM;

    // ---- weight contraction ----
    // warps 0-1 -> r0e (48/64 lanes, 58 it) | warp 2 -> r1o (30 it, waits bar1)
    // warp 3 -> r1e (30 it) | warp 4 -> r0o[0..31] (10 it)
    // warp 5 -> p01 (48 it, lanes 0-9) + bar1.arrive + r0o[32..47] (10 it)
    if (wid < 2) {
        const int w = tid;
        if (w < 48) {
            float acc = 0.0f;
            #pragma unroll
            for (int u = 0; u < 48; u++)
                acc += s_x1[u] * s_W[OW00 + u*48 + w];
            acc *= x20;
            float acc2 = 0.0f;
            #pragma unroll
            for (int u = 0; u < 10; u++)
                acc2 += s_d1o[wid][u] * s_W[OW110 + u*48 + w];
            __stcs(&oz[w], N0E * (acc + ISQ3 * acc2));
        }
    } else if (wid == 2) {
        // wait for warp 5's p01
        asm volatile("bar.sync 1, 64;" ::: "memory");
        if (lid < 30) {
            const int w = lid / 3, j = lid % 3;
            const float x2j = s_x2[1 + j];
            const float p01 = s_p01[w];
            float a10 = 0.0f, a12 = 0.0f, a211 = 0.0f;
            #pragma unroll
            for (int u = 0; u < 10; u++) {
                a10  += s_x1[48 + u*3 + j] * s_W[OW10  + u*10 + w];
                a12  += s_t12[u][j]        * s_W[OW12  + u*10 + w];
                a211 += s_t211[u][j]       * s_W[OW211 + u*10 + w];
            }
            __stcs(&oz[48 + lid],
                   N1O * (ISQ3 * (x2j * p01 + x20 * a10) + a12 + a211));
        }
    } else if (wid == 3) {
        if (lid < 30) {
            const int w = lid / 3, k = lid % 3;
            float a112 = 0.0f, a20 = 0.0f, a22 = 0.0f;
            #pragma unroll
            for (int u = 0; u < 10; u++) {
                a112 += s_t112[u][k]       * s_W[OW112 + u*10 + w];
                a20  += s_x1[78 + u*3 + k] * s_W[OW20  + u*10 + w];
                a22  += s_t22[u][k]        * s_W[OW22  + u*10 + w];
            }
            __stcs(&oz[78 + lid], N1E * (a112 + ISQ3 * x20 * a20 + a22));
        }
    } else if (wid == 4) {
        const int w = lid;          // r0o[0..31]
        float acc = 0.0f;
        #pragma unroll
        for (int u = 0; u < 10; u++)
            acc += s_d1e[0][u] * s_W[OW213 + u*48 + w];
        __stcs(&oz[108 + w], N0O * ISQ3 * acc);
    } else {
        // warp 5: p01 for warp 2, then its r0o slice
        if (lid < 10) {
            const int w = lid;
            float p = 0.0f;
            #pragma unroll
            for (int u = 0; u < 48; u++)
                p += s_x1[u] * s_W[OW01 + u*10 + w];
            s_p01[w] = p;
        }
        asm volatile("bar.arrive 1, 64;" ::: "memory");
        if (lid < 16) {
            const int w = 32 + lid;  // r0o[32..47]
            float acc = 0.0f;
            #pragma unroll
            for (int u = 0; u < 10; u++)
                acc += s_d1e[1][u] * s_W[OW213 + u*48 + w];
            __stcs(&oz[108 + w], N0O * ISQ3 * acc);
        }
    }
}

extern "C" void kernel_launch(void* const* d_in, const int* in_sizes, int n_in,
                              void* d_out, int out_size)
{
    const float* x1 = (const float*)d_in[0];
    const float* x2 = (const float*)d_in[1];
    const float* W  = (const float*)d_in[2];
    float* out = (float*)d_out;

    const int Z = in_sizes[0] / X1DIM;
    tpthird_kernel<<<Z, 192>>>(x1, x2, W, out);
}